// round 15
// baseline (speedup 1.0000x reference)
#include <cuda_runtime.h>
#include <cuda_bf16.h>
#include <cuda_fp16.h>
#include <cstdint>

#define NQ 8192
#define NKV 8192
#define DDIM 512
static constexpr float QSCALE = 0.044194173824159216f; // 1/sqrt(512)

// ---------------- scratch (device globals; no allocation) ----------------
__device__ __align__(256) __half g_xh[NQ * DDIM];     // x fp16
__device__ __align__(256) __half g_domh[NKV * DDIM];  // dom hi
__device__ __align__(256) __half g_doml[NKV * DDIM];  // dom lo
__device__ __align__(256) __half g_wqh[DDIM * DDIM], g_wql[DDIM * DDIM];
__device__ __align__(256) __half g_wkh[DDIM * DDIM], g_wkl[DDIM * DDIM];
__device__ __align__(256) __half g_wvh[DDIM * DDIM];

__device__ __align__(256) __half g_q[NQ * DDIM];      // q fp16 (scaled)
__device__ __align__(256) __half g_k[NKV * DDIM];     // k fp16
__device__ __align__(256) __half g_vt[DDIM * NKV];    // V^T fp16 [512, 8192]
__device__ __align__(256) __half g_p[(size_t)NQ * NKV];  // P = exp(scores), fp16
__device__ float g_lpart[128 * NQ];   // [slot][row]
__device__ float g_linv[NQ];

// ---------------- helpers ----------------
__device__ __forceinline__ uint32_t smem_u32(const void* p) {
    uint32_t a;
    asm("{ .reg .u64 t; cvta.to.shared.u64 t, %1; cvt.u32.u64 %0, t; }"
        : "=r"(a) : "l"(p));
    return a;
}

#define CP16(sa, gp) \
    asm volatile("cp.async.cg.shared.global [%0], [%1], 16;" \
                 :: "r"(sa), "l"(gp) : "memory")
#define CP_COMMIT asm volatile("cp.async.commit_group;" ::: "memory")
#define CP_WAITG(n) asm volatile("cp.async.wait_group %0;" :: "n"(n) : "memory")

#define LDSM_X4(r0, r1, r2, r3, addr) \
    asm volatile("ldmatrix.sync.aligned.m8n8.x4.shared.b16 {%0,%1,%2,%3}, [%4];" \
                 : "=r"(r0), "=r"(r1), "=r"(r2), "=r"(r3) : "r"(addr))

#define MMA_F16(d, a, b) \
    asm volatile("mma.sync.aligned.m16n8k16.row.col.f32.f16.f16.f32 " \
                 "{%0,%1,%2,%3}, {%4,%5,%6,%7}, {%8,%9}, {%0,%1,%2,%3};" \
                 : "+f"((d)[0]), "+f"((d)[1]), "+f"((d)[2]), "+f"((d)[3]) \
                 : "r"((a)[0]), "r"((a)[1]), "r"((a)[2]), "r"((a)[3]), \
                   "r"((b)[0]), "r"((b)[1]))

__device__ __forceinline__ uint2 pack4h(float a, float b, float c, float d) {
    uint2 r;
    __half2 lo = __floats2half2_rn(a, b), hi = __floats2half2_rn(c, d);
    r.x = *(uint32_t*)&lo; r.y = *(uint32_t*)&hi;
    return r;
}

// ---------------------------------------------------------------------------
// presplit: fp32 -> fp16 (and hi/lo splits). 1M threads, 4 floats each.
// ---------------------------------------------------------------------------
__global__ __launch_bounds__(256) void presplit_kernel(
    const float* __restrict__ x, const float* __restrict__ dom,
    const float* __restrict__ Wq, const float* __restrict__ Wk,
    const float* __restrict__ Wv)
{
    const int i = blockIdx.x * 256 + threadIdx.x;   // 0 .. 1048575

    {   // x -> xh (single)
        float4 v = ((const float4*)x)[i];
        ((uint2*)g_xh)[i] = pack4h(v.x, v.y, v.z, v.w);
    }
    {   // dom -> hi/lo
        float4 v = ((const float4*)dom)[i];
        __half h0 = __float2half_rn(v.x), h1 = __float2half_rn(v.y);
        __half h2 = __float2half_rn(v.z), h3 = __float2half_rn(v.w);
        uint2 hh; __half2 p01 = __halves2half2(h0, h1), p23 = __halves2half2(h2, h3);
        hh.x = *(uint32_t*)&p01; hh.y = *(uint32_t*)&p23;
        ((uint2*)g_domh)[i] = hh;
        ((uint2*)g_doml)[i] = pack4h(v.x - __half2float(h0), v.y - __half2float(h1),
                                     v.z - __half2float(h2), v.w - __half2float(h3));
    }
    if (i < (DDIM * DDIM) / 4) {
        {   // Wq hi/lo
            float4 v = ((const float4*)Wq)[i];
            __half h0 = __float2half_rn(v.x), h1 = __float2half_rn(v.y);
            __half h2 = __float2half_rn(v.z), h3 = __float2half_rn(v.w);
            uint2 hh; __half2 p01 = __halves2half2(h0, h1), p23 = __halves2half2(h2, h3);
            hh.x = *(uint32_t*)&p01; hh.y = *(uint32_t*)&p23;
            ((uint2*)g_wqh)[i] = hh;
            ((uint2*)g_wql)[i] = pack4h(v.x - __half2float(h0), v.y - __half2float(h1),
                                        v.z - __half2float(h2), v.w - __half2float(h3));
        }
        {   // Wk hi/lo
            float4 v = ((const float4*)Wk)[i];
            __half h0 = __float2half_rn(v.x), h1 = __float2half_rn(v.y);
            __half h2 = __float2half_rn(v.z), h3 = __float2half_rn(v.w);
            uint2 hh; __half2 p01 = __halves2half2(h0, h1), p23 = __halves2half2(h2, h3);
            hh.x = *(uint32_t*)&p01; hh.y = *(uint32_t*)&p23;
            ((uint2*)g_wkh)[i] = hh;
            ((uint2*)g_wkl)[i] = pack4h(v.x - __half2float(h0), v.y - __half2float(h1),
                                        v.z - __half2float(h2), v.w - __half2float(h3));
        }
        {   // Wv hi only
            float4 v = ((const float4*)Wv)[i];
            ((uint2*)g_wvh)[i] = pack4h(v.x, v.y, v.z, v.w);
        }
    }
}

// ---------------------------------------------------------------------------
// proj_gemm geometry (unchanged): 128x128 tile, warp 32x64, 2-product, occ 2.
// ---------------------------------------------------------------------------
#define ARRP_B   18432           // 128 rows * 144 B
#define STAGE3_B (3 * ARRP_B)    // A | Bh | Bl    (proj, 2-stage)
#define SMEM_PJ  (2 * STAGE3_B)  // 110592

__global__ __launch_bounds__(256, 2) void proj_gemm_kernel(
    const float* __restrict__ bq, const float* __restrict__ bk,
    const float* __restrict__ bv)
{
    constexpr int NC = DDIM / 64;   // 8
    extern __shared__ char smc[];
    const uint32_t smb = smem_u32(smc);

    const int mode = blockIdx.z;
    const int bx = (mode == 2) ? blockIdx.x : blockIdx.y;   // n tile
    const int by = (mode == 2) ? blockIdx.y : blockIdx.x;   // m tile

    const __half* __restrict__ A  = (mode == 0) ? g_xh  : (mode == 1 ? g_domh : g_wvh);
    const __half* __restrict__ Bh = (mode == 0) ? g_wqh : (mode == 1 ? g_wkh : g_domh);
    const __half* __restrict__ Bl = (mode == 0) ? g_wql : (mode == 1 ? g_wkl : g_doml);
    const float* __restrict__ bias = (mode == 0) ? bq : (mode == 1 ? bk : bv);
    __half* __restrict__ outp = (mode == 0) ? g_q : (mode == 1 ? g_k : g_vt);
    const int outLD = (mode == 2) ? NKV : DDIM;
    const float scale = (mode == 0) ? QSCALE : 1.0f;

    const int tid = threadIdx.x;
    const int lane = tid & 31, w = tid >> 5;
    const int wm = w & 3, wn = w >> 2;
    const int rowBase = by * 128;
    const int nBase = bx * 128;

    float acc[2][8][4];
#pragma unroll
    for (int i = 0; i < 2; ++i)
#pragma unroll
        for (int j = 0; j < 8; ++j)
#pragma unroll
            for (int e = 0; e < 4; ++e) acc[i][j][e] = 0.0f;

    auto load_stage = [&](int buf, int kc) {
        const int kBase = kc * 64;
        const uint32_t sb = smb + buf * STAGE3_B;
#pragma unroll
        for (int it = 0; it < 4; ++it) {
            int idx = tid + it * 256;
            int r = idx >> 3, cc = idx & 7;
            uint32_t so = (uint32_t)(r * 144 + cc * 16);
            size_t goA = (size_t)(rowBase + r) * DDIM + kBase + cc * 8;
            size_t goB = (size_t)(nBase + r) * DDIM + kBase + cc * 8;
            CP16(sb + so,              A  + goA);
            CP16(sb + ARRP_B + so,     Bh + goB);
            CP16(sb + 2 * ARRP_B + so, Bl + goB);
        }
        CP_COMMIT;
    };

    const uint32_t aOff = (uint32_t)((wm * 32 + (lane & 15)) * 144 + ((lane >> 4) * 8) * 2);
    const int g = lane >> 3;
    const uint32_t bOff = (uint32_t)((wn * 64 + ((g >> 1) << 3) + (lane & 7)) * 144
                                     + ((g & 1) << 3) * 2);

    load_stage(0, 0);

#pragma unroll 1
    for (int c = 0; c < NC; ++c) {
        CP_WAITG(0);
        __syncthreads();
        if (c + 1 < NC) load_stage((c + 1) & 1, c + 1);

        const uint32_t sb = smb + (c & 1) * STAGE3_B;
        const uint32_t aA = sb + aOff;
        const uint32_t bH = sb + ARRP_B + bOff, bL = sb + 2 * ARRP_B + bOff;
#pragma unroll
        for (int kk = 0; kk < 4; ++kk) {
            uint32_t av[2][4], bh[4][4], bl[4][4];
#pragma unroll
            for (int i = 0; i < 2; ++i)
                LDSM_X4(av[i][0], av[i][1], av[i][2], av[i][3], aA + i * 2304 + kk * 32);
#pragma unroll
            for (int j = 0; j < 4; ++j) {
                LDSM_X4(bh[j][0], bh[j][1], bh[j][2], bh[j][3], bH + j * 2304 + kk * 32);
                LDSM_X4(bl[j][0], bl[j][1], bl[j][2], bl[j][3], bL + j * 2304 + kk * 32);
            }
#pragma unroll
            for (int i = 0; i < 2; ++i)
#pragma unroll
                for (int jj = 0; jj < 8; ++jj) {
                    MMA_F16(acc[i][jj], av[i], &bh[jj >> 1][(jj & 1) * 2]);
                    MMA_F16(acc[i][jj], av[i], &bl[jj >> 1][(jj & 1) * 2]);
                }
        }
    }

    // ---- epilogue: bias (+scale) -> fp16 store ----
    if (mode == 2) {
#pragma unroll
        for (int i = 0; i < 2; ++i) {
            const int row0 = rowBase + wm * 32 + i * 16 + (lane >> 2);
            const float b0 = bias[row0], b1 = bias[row0 + 8];
#pragma unroll
            for (int jj = 0; jj < 8; ++jj) {
                const int col = nBase + wn * 64 + jj * 8 + (lane & 3) * 2;
                *(__half2*)&outp[(size_t)row0 * outLD + col] =
                    __floats2half2_rn(acc[i][jj][0] + b0, acc[i][jj][1] + b0);
                *(__half2*)&outp[(size_t)(row0 + 8) * outLD + col] =
                    __floats2half2_rn(acc[i][jj][2] + b1, acc[i][jj][3] + b1);
            }
        }
    } else {
#pragma unroll
        for (int i = 0; i < 2; ++i) {
            const int row0 = rowBase + wm * 32 + i * 16 + (lane >> 2);
#pragma unroll
            for (int jj = 0; jj < 8; ++jj) {
                const int col = nBase + wn * 64 + jj * 8 + (lane & 3) * 2;
                const float bc0 = bias[col], bc1 = bias[col + 1];
                *(__half2*)&outp[(size_t)row0 * outLD + col] =
                    __floats2half2_rn((acc[i][jj][0] + bc0) * scale,
                                      (acc[i][jj][1] + bc1) * scale);
                *(__half2*)&outp[(size_t)(row0 + 8) * outLD + col] =
                    __floats2half2_rn((acc[i][jj][2] + bc0) * scale,
                                      (acc[i][jj][3] + bc1) * scale);
            }
        }
    }
}

// ---------------------------------------------------------------------------
// Big-GEMM geometry: 128x256 CTA tile, 8 warps (2m x 4n), warp 64x64, BK=64,
// 4-stage cp.async pipeline, occ 1. LDSM:MMA ratio = 8:32 per k16.
// ---------------------------------------------------------------------------
#define ARRA_B   18432           // 128 rows * 144 B (A)
#define ARRB_B   36864           // 256 rows * 144 B (B)
#define STAGE_B  (ARRA_B + ARRB_B)   // 55296
#define SMEM_GB  (4 * STAGE_B)       // 221184

// ---- GEMM1: P = exp(q k^T), K=512 ----
__global__ __launch_bounds__(256, 1) void gemm1_kernel()
{
    constexpr int NC = DDIM / 64;   // 8
    extern __shared__ char smc[];
    const uint32_t smb = smem_u32(smc);

    const int tid = threadIdx.x;
    const int lane = tid & 31, w = tid >> 5;
    const int wm = w & 1, wn = w >> 1;
    const int rowBase = blockIdx.y * 128;
    const int nBase = blockIdx.x * 256;

    float acc[4][8][4];
#pragma unroll
    for (int i = 0; i < 4; ++i)
#pragma unroll
        for (int j = 0; j < 8; ++j)
#pragma unroll
            for (int e = 0; e < 4; ++e) acc[i][j][e] = 0.0f;

    auto load_stage = [&](int buf, int kc) {
        const int kBase = kc * 64;
        const uint32_t sb = smb + buf * STAGE_B;
#pragma unroll
        for (int it = 0; it < 4; ++it) {           // A: 128 rows
            int idx = tid + it * 256;
            int r = idx >> 3, cc = idx & 7;
            CP16(sb + r * 144 + cc * 16,
                 g_q + (size_t)(rowBase + r) * DDIM + kBase + cc * 8);
        }
#pragma unroll
        for (int it = 0; it < 8; ++it) {           // B: 256 rows
            int idx = tid + it * 256;
            int r = idx >> 3, cc = idx & 7;
            CP16(sb + ARRA_B + r * 144 + cc * 16,
                 g_k + (size_t)(nBase + r) * DDIM + kBase + cc * 8);
        }
        CP_COMMIT;
    };

    const uint32_t aOff = (uint32_t)((wm * 64 + (lane & 15)) * 144 + ((lane >> 4) * 8) * 2);
    const int g = lane >> 3;
    const uint32_t bOff = (uint32_t)((wn * 64 + ((g >> 1) << 3) + (lane & 7)) * 144
                                     + ((g & 1) << 3) * 2);

    load_stage(0, 0);
    load_stage(1, 1);
    load_stage(2, 2);

#pragma unroll 1
    for (int c = 0; c < NC; ++c) {
        if (c < NC - 2)      { CP_WAITG(2); }
        else if (c == NC - 2){ CP_WAITG(1); }
        else                 { CP_WAITG(0); }
        __syncthreads();
        if (c + 3 < NC) load_stage((c + 3) & 3, c + 3);

        const uint32_t sb = smb + (c & 3) * STAGE_B;
        const uint32_t aA = sb + aOff;
        const uint32_t bB = sb + ARRA_B + bOff;
#pragma unroll
        for (int kk = 0; kk < 4; ++kk) {
            uint32_t af[4][4], bf[4][4];
#pragma unroll
            for (int i = 0; i < 4; ++i)
                LDSM_X4(af[i][0], af[i][1], af[i][2], af[i][3], aA + i * 2304 + kk * 32);
#pragma unroll
            for (int j = 0; j < 4; ++j)
                LDSM_X4(bf[j][0], bf[j][1], bf[j][2], bf[j][3], bB + j * 2304 + kk * 32);
#pragma unroll
            for (int i = 0; i < 4; ++i)
#pragma unroll
                for (int jj = 0; jj < 8; ++jj)
                    MMA_F16(acc[i][jj], af[i], &bf[jj >> 1][(jj & 1) * 2]);
        }
    }

    // ---- epilogue: P = exp(acc) -> fp16, plus deterministic row-sum partials
    float ls[4][2];
#pragma unroll
    for (int i = 0; i < 4; ++i) { ls[i][0] = 0.0f; ls[i][1] = 0.0f; }
#pragma unroll
    for (int i = 0; i < 4; ++i) {
        const int row0 = rowBase + wm * 64 + i * 16 + (lane >> 2);
#pragma unroll
        for (int jj = 0; jj < 8; ++jj) {
            const int col = nBase + wn * 64 + jj * 8 + (lane & 3) * 2;
            float p0 = __expf(acc[i][jj][0]);
            float p1 = __expf(acc[i][jj][1]);
            float p2 = __expf(acc[i][jj][2]);
            float p3 = __expf(acc[i][jj][3]);
            ls[i][0] += p0 + p1;
            ls[i][1] += p2 + p3;
            *(__half2*)&g_p[(size_t)row0 * NKV + col] = __floats2half2_rn(p0, p1);
            *(__half2*)&g_p[(size_t)(row0 + 8) * NKV + col] = __floats2half2_rn(p2, p3);
        }
    }
    const int slot = blockIdx.x * 4 + wn;   // 32 n-tiles * 4 wn = 128 slots
#pragma unroll
    for (int i = 0; i < 4; ++i)
#pragma unroll
        for (int pr = 0; pr < 2; ++pr) {
            float s = ls[i][pr];
            s += __shfl_xor_sync(0xffffffffu, s, 1);
            s += __shfl_xor_sync(0xffffffffu, s, 2);
            if ((lane & 3) == 0) {
                int row = rowBase + wm * 64 + i * 16 + (lane >> 2) + pr * 8;
                g_lpart[(size_t)slot * NQ + row] = s;
            }
        }
}

// ---- GEMM2: O = (P V) * linv, K=8192 ----
__global__ __launch_bounds__(256, 1) void gemm2_kernel(float* __restrict__ outp)
{
    constexpr int NC = NKV / 64;    // 128
    extern __shared__ char smc[];
    const uint32_t smb = smem_u32(smc);

    const int tid = threadIdx.x;
    const int lane = tid & 31, w = tid >> 5;
    const int wm = w & 1, wn = w >> 1;
    const int rowBase = blockIdx.y * 128;
    const int nBase = blockIdx.x * 256;

    float acc[4][8][4];
#pragma unroll
    for (int i = 0; i < 4; ++i)
#pragma unroll
        for (int j = 0; j < 8; ++j)
#pragma unroll
            for (int e = 0; e < 4; ++e) acc[i][j][e] = 0.0f;

    auto load_stage = [&](int buf, int kc) {
        const int kBase = kc * 64;
        const uint32_t sb = smb + buf * STAGE_B;
#pragma unroll
        for (int it = 0; it < 4; ++it) {           // A = P: 128 rows
            int idx = tid + it * 256;
            int r = idx >> 3, cc = idx & 7;
            CP16(sb + r * 144 + cc * 16,
                 g_p + (size_t)(rowBase + r) * NKV + kBase + cc * 8);
        }
#pragma unroll
        for (int it = 0; it < 8; ++it) {           // B = V^T: 256 rows
            int idx = tid + it * 256;
            int r = idx >> 3, cc = idx & 7;
            CP16(sb + ARRA_B + r * 144 + cc * 16,
                 g_vt + (size_t)(nBase + r) * NKV + kBase + cc * 8);
        }
        CP_COMMIT;
    };

    const uint32_t aOff = (uint32_t)((wm * 64 + (lane & 15)) * 144 + ((lane >> 4) * 8) * 2);
    const int g = lane >> 3;
    const uint32_t bOff = (uint32_t)((wn * 64 + ((g >> 1) << 3) + (lane & 7)) * 144
                                     + ((g & 1) << 3) * 2);

    load_stage(0, 0);
    load_stage(1, 1);
    load_stage(2, 2);

#pragma unroll 1
    for (int c = 0; c < NC; ++c) {
        if (c < NC - 2)      { CP_WAITG(2); }
        else if (c == NC - 2){ CP_WAITG(1); }
        else                 { CP_WAITG(0); }
        __syncthreads();
        if (c + 3 < NC) load_stage((c + 3) & 3, c + 3);

        const uint32_t sb = smb + (c & 3) * STAGE_B;
        const uint32_t aA = sb + aOff;
        const uint32_t bB = sb + ARRA_B + bOff;
#pragma unroll
        for (int kk = 0; kk < 4; ++kk) {
            uint32_t af[4][4], bf[4][4];
#pragma unroll
            for (int i = 0; i < 4; ++i)
                LDSM_X4(af[i][0], af[i][1], af[i][2], af[i][3], aA + i * 2304 + kk * 32);
#pragma unroll
            for (int j = 0; j < 4; ++j)
                LDSM_X4(bf[j][0], bf[j][1], bf[j][2], bf[j][3], bB + j * 2304 + kk * 32);
#pragma unroll
            for (int i = 0; i < 4; ++i)
#pragma unroll
                for (int jj = 0; jj < 8; ++jj)
                    MMA_F16(acc[i][jj], af[i], &bf[jj >> 1][(jj & 1) * 2]);
        }
    }

    // ---- epilogue: out = acc * linv[row]
#pragma unroll
    for (int i = 0; i < 4; ++i) {
        const int row0 = rowBase + wm * 64 + i * 16 + (lane >> 2);
        const float inv0 = g_linv[row0];
        const float inv1 = g_linv[row0 + 8];
#pragma unroll
        for (int jj = 0; jj < 8; ++jj) {
            const int col = nBase + wn * 64 + jj * 8 + (lane & 3) * 2;
            float2 r0, r1;
            r0.x = acc[i][jj][0] * inv0; r0.y = acc[i][jj][1] * inv0;
            r1.x = acc[i][jj][2] * inv1; r1.y = acc[i][jj][3] * inv1;
            *(float2*)&outp[(size_t)row0 * DDIM + col] = r0;
            *(float2*)&outp[(size_t)(row0 + 8) * DDIM + col] = r1;
        }
    }
}

// ---------------------------------------------------------------------------
__global__ void lred_kernel()
{
    int row = blockIdx.x * 256 + threadIdx.x;
    float s = 0.0f;
#pragma unroll 8
    for (int j = 0; j < 128; ++j) s += g_lpart[(size_t)j * NQ + row];
    g_linv[row] = 1.0f / s;
}

// ---------------------------------------------------------------------------
extern "C" void kernel_launch(void* const* d_in, const int* in_sizes, int n_in,
                              void* d_out, int out_size)
{
    const float* x   = (const float*)d_in[0];
    const float* dom = (const float*)d_in[1];
    const float* Wq  = (const float*)d_in[2];
    const float* bq  = (const float*)d_in[3];
    const float* Wk  = (const float*)d_in[4];
    const float* bk  = (const float*)d_in[5];
    const float* Wv  = (const float*)d_in[6];
    const float* bv  = (const float*)d_in[7];
    float* out = (float*)d_out;

    cudaFuncSetAttribute(proj_gemm_kernel,
                         cudaFuncAttributeMaxDynamicSharedMemorySize, SMEM_PJ);
    cudaFuncSetAttribute(gemm1_kernel,
                         cudaFuncAttributeMaxDynamicSharedMemorySize, SMEM_GB);
    cudaFuncSetAttribute(gemm2_kernel,
                         cudaFuncAttributeMaxDynamicSharedMemorySize, SMEM_GB);

    presplit_kernel<<<(NQ * DDIM / 4) / 256, 256>>>(x, dom, Wq, Wk, Wv);

    // q, k, vt projections on tensor cores (z: 0=q, 1=k, 2=vt)
    proj_gemm_kernel<<<dim3(64, 4, 3), 256, SMEM_PJ>>>(bq, bk, bv);

    // P = exp(q k^T): 128x256 tiles
    gemm1_kernel<<<dim3(NKV / 256, NQ / 128), 256, SMEM_GB>>>();

    lred_kernel<<<NQ / 256, 256>>>();

    // O = (P V) * linv: 128x256 tiles
    gemm2_kernel<<<dim3(DDIM / 256, NQ / 128), 256, SMEM_GB>>>(out);
}

// round 16
// speedup vs baseline: 1.1020x; 1.1020x over previous
#include <cuda_runtime.h>
#include <cuda_bf16.h>
#include <cuda_fp16.h>
#include <cstdint>

#define NQ 8192
#define NKV 8192
#define DDIM 512
static constexpr float QSCALE = 0.044194173824159216f; // 1/sqrt(512)

// ---------------- scratch (device globals; no allocation) ----------------
__device__ __align__(256) __half g_xh[NQ * DDIM];     // x fp16
__device__ __align__(256) __half g_domh[NKV * DDIM];  // dom hi
__device__ __align__(256) __half g_doml[NKV * DDIM];  // dom lo
__device__ __align__(256) __half g_wqh[DDIM * DDIM];  // Wq fp16
__device__ __align__(256) __half g_wkh[DDIM * DDIM];  // Wk fp16
__device__ __align__(256) __half g_wvh[DDIM * DDIM];  // Wv fp16

__device__ __align__(256) __half g_q[NQ * DDIM];      // q fp16 (scaled)
__device__ __align__(256) __half g_k[NKV * DDIM];     // k fp16
__device__ __align__(256) __half g_vt[DDIM * NKV];    // V^T fp16 [512, 8192]
__device__ __align__(256) __half g_p[(size_t)NQ * NKV];  // P = exp(scores), fp16
__device__ float g_lpart[128 * NQ];   // [slot][row]
__device__ float g_linv[NQ];

// ---------------- helpers ----------------
__device__ __forceinline__ uint32_t smem_u32(const void* p) {
    uint32_t a;
    asm("{ .reg .u64 t; cvta.to.shared.u64 t, %1; cvt.u32.u64 %0, t; }"
        : "=r"(a) : "l"(p));
    return a;
}

#define CP16(sa, gp) \
    asm volatile("cp.async.cg.shared.global [%0], [%1], 16;" \
                 :: "r"(sa), "l"(gp) : "memory")
#define CP_COMMIT asm volatile("cp.async.commit_group;" ::: "memory")
#define CP_WAITG(n) asm volatile("cp.async.wait_group %0;" :: "n"(n) : "memory")

#define LDSM_X4(r0, r1, r2, r3, addr) \
    asm volatile("ldmatrix.sync.aligned.m8n8.x4.shared.b16 {%0,%1,%2,%3}, [%4];" \
                 : "=r"(r0), "=r"(r1), "=r"(r2), "=r"(r3) : "r"(addr))

#define MMA_F16(d, a, b) \
    asm volatile("mma.sync.aligned.m16n8k16.row.col.f32.f16.f16.f32 " \
                 "{%0,%1,%2,%3}, {%4,%5,%6,%7}, {%8,%9}, {%0,%1,%2,%3};" \
                 : "+f"((d)[0]), "+f"((d)[1]), "+f"((d)[2]), "+f"((d)[3]) \
                 : "r"((a)[0]), "r"((a)[1]), "r"((a)[2]), "r"((a)[3]), \
                   "r"((b)[0]), "r"((b)[1]))

__device__ __forceinline__ uint2 pack4h(float a, float b, float c, float d) {
    uint2 r;
    __half2 lo = __floats2half2_rn(a, b), hi = __floats2half2_rn(c, d);
    r.x = *(uint32_t*)&lo; r.y = *(uint32_t*)&hi;
    return r;
}

// ---------------------------------------------------------------------------
// presplit: fp32 -> fp16 (dom also hi/lo). 1M threads, 4 floats each.
// ---------------------------------------------------------------------------
__global__ __launch_bounds__(256) void presplit_kernel(
    const float* __restrict__ x, const float* __restrict__ dom,
    const float* __restrict__ Wq, const float* __restrict__ Wk,
    const float* __restrict__ Wv)
{
    const int i = blockIdx.x * 256 + threadIdx.x;   // 0 .. 1048575

    {   // x -> xh (single)
        float4 v = ((const float4*)x)[i];
        ((uint2*)g_xh)[i] = pack4h(v.x, v.y, v.z, v.w);
    }
    {   // dom -> hi/lo
        float4 v = ((const float4*)dom)[i];
        __half h0 = __float2half_rn(v.x), h1 = __float2half_rn(v.y);
        __half h2 = __float2half_rn(v.z), h3 = __float2half_rn(v.w);
        uint2 hh; __half2 p01 = __halves2half2(h0, h1), p23 = __halves2half2(h2, h3);
        hh.x = *(uint32_t*)&p01; hh.y = *(uint32_t*)&p23;
        ((uint2*)g_domh)[i] = hh;
        ((uint2*)g_doml)[i] = pack4h(v.x - __half2float(h0), v.y - __half2float(h1),
                                     v.z - __half2float(h2), v.w - __half2float(h3));
    }
    if (i < (DDIM * DDIM) / 4) {
        {   // Wq single
            float4 v = ((const float4*)Wq)[i];
            ((uint2*)g_wqh)[i] = pack4h(v.x, v.y, v.z, v.w);
        }
        {   // Wk single
            float4 v = ((const float4*)Wk)[i];
            ((uint2*)g_wkh)[i] = pack4h(v.x, v.y, v.z, v.w);
        }
        {   // Wv single
            float4 v = ((const float4*)Wv)[i];
            ((uint2*)g_wvh)[i] = pack4h(v.x, v.y, v.z, v.w);
        }
    }
}

// ---------------------------------------------------------------------------
// proj_gemm: 128x128 tile, warp 32x64, 2-stage, occ 2.
//   z=0: q  = (xh @ Wqh^T + bq) * QSCALE     single product   [8192,512]
//   z=1: k  =  domh @ Wkh^T + bk             single product   [8192,512]
//   z=2: vt =  Wvh @ (domh+doml)^T + bv      dual product     [512,8192] (V^T)
// ---------------------------------------------------------------------------
#define ARRP_B   18432           // 128 rows * 144 B
#define STAGE3_B (3 * ARRP_B)    // A | Bh | Bl
#define SMEM_PJ  (2 * STAGE3_B)  // 110592

__global__ __launch_bounds__(256, 2) void proj_gemm_kernel(
    const float* __restrict__ bq, const float* __restrict__ bk,
    const float* __restrict__ bv)
{
    constexpr int NC = DDIM / 64;   // 8
    extern __shared__ char smc[];
    const uint32_t smb = smem_u32(smc);

    const int mode = blockIdx.z;
    const bool dual = (mode == 2);
    const int bx = (mode == 2) ? blockIdx.x : blockIdx.y;   // n tile
    const int by = (mode == 2) ? blockIdx.y : blockIdx.x;   // m tile

    const __half* __restrict__ A  = (mode == 0) ? g_xh  : (mode == 1 ? g_domh : g_wvh);
    const __half* __restrict__ Bh = (mode == 0) ? g_wqh : (mode == 1 ? g_wkh : g_domh);
    const __half* __restrict__ Bl = g_doml;                 // used only when dual
    const float* __restrict__ bias = (mode == 0) ? bq : (mode == 1 ? bk : bv);
    __half* __restrict__ outp = (mode == 0) ? g_q : (mode == 1 ? g_k : g_vt);
    const int outLD = (mode == 2) ? NKV : DDIM;
    const float scale = (mode == 0) ? QSCALE : 1.0f;

    const int tid = threadIdx.x;
    const int lane = tid & 31, w = tid >> 5;
    const int wm = w & 3, wn = w >> 2;
    const int rowBase = by * 128;
    const int nBase = bx * 128;

    float acc[2][8][4];
#pragma unroll
    for (int i = 0; i < 2; ++i)
#pragma unroll
        for (int j = 0; j < 8; ++j)
#pragma unroll
            for (int e = 0; e < 4; ++e) acc[i][j][e] = 0.0f;

    auto load_stage = [&](int buf, int kc) {
        const int kBase = kc * 64;
        const uint32_t sb = smb + buf * STAGE3_B;
#pragma unroll
        for (int it = 0; it < 4; ++it) {
            int idx = tid + it * 256;
            int r = idx >> 3, cc = idx & 7;
            uint32_t so = (uint32_t)(r * 144 + cc * 16);
            size_t goA = (size_t)(rowBase + r) * DDIM + kBase + cc * 8;
            size_t goB = (size_t)(nBase + r) * DDIM + kBase + cc * 8;
            CP16(sb + so,          A  + goA);
            CP16(sb + ARRP_B + so, Bh + goB);
            if (dual) CP16(sb + 2 * ARRP_B + so, Bl + goB);
        }
        CP_COMMIT;
    };

    const uint32_t aOff = (uint32_t)((wm * 32 + (lane & 15)) * 144 + ((lane >> 4) * 8) * 2);
    const int g = lane >> 3;
    const uint32_t bOff = (uint32_t)((wn * 64 + ((g >> 1) << 3) + (lane & 7)) * 144
                                     + ((g & 1) << 3) * 2);

    load_stage(0, 0);

#pragma unroll 1
    for (int c = 0; c < NC; ++c) {
        CP_WAITG(0);
        __syncthreads();
        if (c + 1 < NC) load_stage((c + 1) & 1, c + 1);

        const uint32_t sb = smb + (c & 1) * STAGE3_B;
        const uint32_t aA = sb + aOff;
        const uint32_t bH = sb + ARRP_B + bOff, bL = sb + 2 * ARRP_B + bOff;
#pragma unroll
        for (int kk = 0; kk < 4; ++kk) {
            uint32_t av[2][4], bh[4][4], bl[4][4];
#pragma unroll
            for (int i = 0; i < 2; ++i)
                LDSM_X4(av[i][0], av[i][1], av[i][2], av[i][3], aA + i * 2304 + kk * 32);
#pragma unroll
            for (int j = 0; j < 4; ++j)
                LDSM_X4(bh[j][0], bh[j][1], bh[j][2], bh[j][3], bH + j * 2304 + kk * 32);
            if (dual) {
#pragma unroll
                for (int j = 0; j < 4; ++j)
                    LDSM_X4(bl[j][0], bl[j][1], bl[j][2], bl[j][3], bL + j * 2304 + kk * 32);
            }
#pragma unroll
            for (int i = 0; i < 2; ++i)
#pragma unroll
                for (int jj = 0; jj < 8; ++jj)
                    MMA_F16(acc[i][jj], av[i], &bh[jj >> 1][(jj & 1) * 2]);
            if (dual) {
#pragma unroll
                for (int i = 0; i < 2; ++i)
#pragma unroll
                    for (int jj = 0; jj < 8; ++jj)
                        MMA_F16(acc[i][jj], av[i], &bl[jj >> 1][(jj & 1) * 2]);
            }
        }
    }

    // ---- epilogue: bias (+scale) -> fp16 store ----
    if (mode == 2) {
#pragma unroll
        for (int i = 0; i < 2; ++i) {
            const int row0 = rowBase + wm * 32 + i * 16 + (lane >> 2);
            const float b0 = bias[row0], b1 = bias[row0 + 8];
#pragma unroll
            for (int jj = 0; jj < 8; ++jj) {
                const int col = nBase + wn * 64 + jj * 8 + (lane & 3) * 2;
                *(__half2*)&outp[(size_t)row0 * outLD + col] =
                    __floats2half2_rn(acc[i][jj][0] + b0, acc[i][jj][1] + b0);
                *(__half2*)&outp[(size_t)(row0 + 8) * outLD + col] =
                    __floats2half2_rn(acc[i][jj][2] + b1, acc[i][jj][3] + b1);
            }
        }
    } else {
#pragma unroll
        for (int i = 0; i < 2; ++i) {
            const int row0 = rowBase + wm * 32 + i * 16 + (lane >> 2);
#pragma unroll
            for (int jj = 0; jj < 8; ++jj) {
                const int col = nBase + wn * 64 + jj * 8 + (lane & 3) * 2;
                const float bc0 = bias[col], bc1 = bias[col + 1];
                *(__half2*)&outp[(size_t)row0 * outLD + col] =
                    __floats2half2_rn((acc[i][jj][0] + bc0) * scale,
                                      (acc[i][jj][1] + bc1) * scale);
                *(__half2*)&outp[(size_t)(row0 + 8) * outLD + col] =
                    __floats2half2_rn((acc[i][jj][2] + bc0) * scale,
                                      (acc[i][jj][3] + bc1) * scale);
            }
        }
    }
}

// ---------------------------------------------------------------------------
// Big-GEMM geometry (round-12 winner): 128x128 tile, 8 warps (4m x 2n),
// warp 32x64, BK=64, 3-stage cp.async, 2 CTAs/SM, single fp16 product.
// ---------------------------------------------------------------------------
#define ARR_B    18432           // 128 rows * 144 B
#define STAGE_B  (2 * ARR_B)     // A | B
#define SMEM_GB  (3 * STAGE_B)   // 110592

// ---- GEMM1: P = exp(q k^T), K=512 ----
__global__ __launch_bounds__(256, 2) void gemm1_kernel()
{
    constexpr int NC = DDIM / 64;   // 8
    extern __shared__ char smc[];
    const uint32_t smb = smem_u32(smc);

    const int tid = threadIdx.x;
    const int lane = tid & 31, w = tid >> 5;
    const int wm = w & 3, wn = w >> 2;
    const int rowBase = blockIdx.y * 128;
    const int nBase = blockIdx.x * 128;

    float acc[2][8][4];
#pragma unroll
    for (int i = 0; i < 2; ++i)
#pragma unroll
        for (int j = 0; j < 8; ++j)
#pragma unroll
            for (int e = 0; e < 4; ++e) acc[i][j][e] = 0.0f;

    auto load_stage = [&](int buf, int kc) {
        const int kBase = kc * 64;
        const uint32_t sb = smb + buf * STAGE_B;
#pragma unroll
        for (int it = 0; it < 4; ++it) {
            int idx = tid + it * 256;
            int r = idx >> 3, cc = idx & 7;
            uint32_t so = (uint32_t)(r * 144 + cc * 16);
            CP16(sb + so,         g_q + (size_t)(rowBase + r) * DDIM + kBase + cc * 8);
            CP16(sb + ARR_B + so, g_k + (size_t)(nBase + r) * DDIM + kBase + cc * 8);
        }
        CP_COMMIT;
    };

    const uint32_t aOff = (uint32_t)((wm * 32 + (lane & 15)) * 144 + ((lane >> 4) * 8) * 2);
    const int g = lane >> 3;
    const uint32_t bOff = (uint32_t)((wn * 64 + ((g >> 1) << 3) + (lane & 7)) * 144
                                     + ((g & 1) << 3) * 2);

    load_stage(0, 0);
    load_stage(1, 1);

#pragma unroll 1
    for (int c = 0; c < NC; ++c) {
        if (c == NC - 1) { CP_WAITG(0); } else { CP_WAITG(1); }
        __syncthreads();
        if (c + 2 < NC) load_stage((c + 2) % 3, c + 2);

        const uint32_t sb = smb + (c % 3) * STAGE_B;
        const uint32_t aA = sb + aOff;
        const uint32_t bB = sb + ARR_B + bOff;
#pragma unroll
        for (int kk = 0; kk < 4; ++kk) {
            uint32_t aq[2][4], kb[4][4];
#pragma unroll
            for (int i = 0; i < 2; ++i)
                LDSM_X4(aq[i][0], aq[i][1], aq[i][2], aq[i][3], aA + i * 2304 + kk * 32);
#pragma unroll
            for (int j = 0; j < 4; ++j)
                LDSM_X4(kb[j][0], kb[j][1], kb[j][2], kb[j][3], bB + j * 2304 + kk * 32);
#pragma unroll
            for (int i = 0; i < 2; ++i)
#pragma unroll
                for (int jj = 0; jj < 8; ++jj)
                    MMA_F16(acc[i][jj], aq[i], &kb[jj >> 1][(jj & 1) * 2]);
        }
    }

    // ---- epilogue: P = exp(acc) -> fp16, plus deterministic row-sum partials
    float ls[2][2] = {{0.0f, 0.0f}, {0.0f, 0.0f}};
#pragma unroll
    for (int i = 0; i < 2; ++i) {
        const int row0 = rowBase + wm * 32 + i * 16 + (lane >> 2);
#pragma unroll
        for (int jj = 0; jj < 8; ++jj) {
            const int col = nBase + wn * 64 + jj * 8 + (lane & 3) * 2;
            float p0 = __expf(acc[i][jj][0]);
            float p1 = __expf(acc[i][jj][1]);
            float p2 = __expf(acc[i][jj][2]);
            float p3 = __expf(acc[i][jj][3]);
            ls[i][0] += p0 + p1;
            ls[i][1] += p2 + p3;
            *(__half2*)&g_p[(size_t)row0 * NKV + col] = __floats2half2_rn(p0, p1);
            *(__half2*)&g_p[(size_t)(row0 + 8) * NKV + col] = __floats2half2_rn(p2, p3);
        }
    }
    const int slot = blockIdx.x * 2 + wn;
#pragma unroll
    for (int i = 0; i < 2; ++i)
#pragma unroll
        for (int pr = 0; pr < 2; ++pr) {
            float s = ls[i][pr];
            s += __shfl_xor_sync(0xffffffffu, s, 1);
            s += __shfl_xor_sync(0xffffffffu, s, 2);
            if ((lane & 3) == 0) {
                int row = rowBase + wm * 32 + i * 16 + (lane >> 2) + pr * 8;
                g_lpart[(size_t)slot * NQ + row] = s;
            }
        }
}

// ---- GEMM2: O = (P V) * linv, K=8192 ----
__global__ __launch_bounds__(256, 2) void gemm2_kernel(float* __restrict__ outp)
{
    constexpr int NC = NKV / 64;    // 128
    extern __shared__ char smc[];
    const uint32_t smb = smem_u32(smc);

    const int tid = threadIdx.x;
    const int lane = tid & 31, w = tid >> 5;
    const int wm = w & 3, wn = w >> 2;
    const int rowBase = blockIdx.y * 128;
    const int nBase = blockIdx.x * 128;

    float acc[2][8][4];
#pragma unroll
    for (int i = 0; i < 2; ++i)
#pragma unroll
        for (int j = 0; j < 8; ++j)
#pragma unroll
            for (int e = 0; e < 4; ++e) acc[i][j][e] = 0.0f;

    auto load_stage = [&](int buf, int kc) {
        const int kBase = kc * 64;
        const uint32_t sb = smb + buf * STAGE_B;
#pragma unroll
        for (int it = 0; it < 4; ++it) {
            int idx = tid + it * 256;
            int r = idx >> 3, cc = idx & 7;
            uint32_t so = (uint32_t)(r * 144 + cc * 16);
            CP16(sb + so,         g_p + (size_t)(rowBase + r) * NKV + kBase + cc * 8);
            CP16(sb + ARR_B + so, g_vt + (size_t)(nBase + r) * NKV + kBase + cc * 8);
        }
        CP_COMMIT;
    };

    const uint32_t aOff = (uint32_t)((wm * 32 + (lane & 15)) * 144 + ((lane >> 4) * 8) * 2);
    const int g = lane >> 3;
    const uint32_t bOff = (uint32_t)((wn * 64 + ((g >> 1) << 3) + (lane & 7)) * 144
                                     + ((g & 1) << 3) * 2);

    load_stage(0, 0);
    load_stage(1, 1);

#pragma unroll 1
    for (int c = 0; c < NC; ++c) {
        if (c == NC - 1) { CP_WAITG(0); } else { CP_WAITG(1); }
        __syncthreads();
        if (c + 2 < NC) load_stage((c + 2) % 3, c + 2);

        const uint32_t sb = smb + (c % 3) * STAGE_B;
        const uint32_t aP = sb + aOff;
        const uint32_t bV = sb + ARR_B + bOff;
#pragma unroll
        for (int kk = 0; kk < 4; ++kk) {
            uint32_t ap[2][4], vb[4][4];
#pragma unroll
            for (int i = 0; i < 2; ++i)
                LDSM_X4(ap[i][0], ap[i][1], ap[i][2], ap[i][3], aP + i * 2304 + kk * 32);
#pragma unroll
            for (int j = 0; j < 4; ++j)
                LDSM_X4(vb[j][0], vb[j][1], vb[j][2], vb[j][3], bV + j * 2304 + kk * 32);
#pragma unroll
            for (int i = 0; i < 2; ++i)
#pragma unroll
                for (int jj = 0; jj < 8; ++jj)
                    MMA_F16(acc[i][jj], ap[i], &vb[jj >> 1][(jj & 1) * 2]);
        }
    }

    // ---- epilogue: out = acc * linv[row]
#pragma unroll
    for (int i = 0; i < 2; ++i) {
        const int row0 = rowBase + wm * 32 + i * 16 + (lane >> 2);
        const float inv0 = g_linv[row0];
        const float inv1 = g_linv[row0 + 8];
#pragma unroll
        for (int jj = 0; jj < 8; ++jj) {
            const int col = nBase + wn * 64 + jj * 8 + (lane & 3) * 2;
            float2 r0, r1;
            r0.x = acc[i][jj][0] * inv0; r0.y = acc[i][jj][1] * inv0;
            r1.x = acc[i][jj][2] * inv1; r1.y = acc[i][jj][3] * inv1;
            *(float2*)&outp[(size_t)row0 * DDIM + col] = r0;
            *(float2*)&outp[(size_t)(row0 + 8) * DDIM + col] = r1;
        }
    }
}

// ---------------------------------------------------------------------------
__global__ void lred_kernel()
{
    int row = blockIdx.x * 256 + threadIdx.x;
    float s = 0.0f;
#pragma unroll 8
    for (int j = 0; j < 128; ++j) s += g_lpart[(size_t)j * NQ + row];
    g_linv[row] = 1.0f / s;
}

// ---------------------------------------------------------------------------
extern "C" void kernel_launch(void* const* d_in, const int* in_sizes, int n_in,
                              void* d_out, int out_size)
{
    const float* x   = (const float*)d_in[0];
    const float* dom = (const float*)d_in[1];
    const float* Wq  = (const float*)d_in[2];
    const float* bq  = (const float*)d_in[3];
    const float* Wk  = (const float*)d_in[4];
    const float* bk  = (const float*)d_in[5];
    const float* Wv  = (const float*)d_in[6];
    const float* bv  = (const float*)d_in[7];
    float* out = (float*)d_out;

    cudaFuncSetAttribute(proj_gemm_kernel,
                         cudaFuncAttributeMaxDynamicSharedMemorySize, SMEM_PJ);
    cudaFuncSetAttribute(gemm1_kernel,
                         cudaFuncAttributeMaxDynamicSharedMemorySize, SMEM_GB);
    cudaFuncSetAttribute(gemm2_kernel,
                         cudaFuncAttributeMaxDynamicSharedMemorySize, SMEM_GB);

    presplit_kernel<<<(NQ * DDIM / 4) / 256, 256>>>(x, dom, Wq, Wk, Wv);

    // q, k, vt projections on tensor cores (z: 0=q, 1=k, 2=vt)
    proj_gemm_kernel<<<dim3(64, 4, 3), 256, SMEM_PJ>>>(bq, bk, bv);

    // P = exp(q k^T)
    gemm1_kernel<<<dim3(NKV / 128, NQ / 128), 256, SMEM_GB>>>();

    lred_kernel<<<NQ / 256, 256>>>();

    // O = (P V) * linv
    gemm2_kernel<<<dim3(DDIM / 128, NQ / 128), 256, SMEM_GB>>>(out);
}

// round 17
// speedup vs baseline: 1.1483x; 1.0420x over previous
#include <cuda_runtime.h>
#include <cuda_bf16.h>
#include <cuda_fp16.h>
#include <cstdint>

#define NQ 8192
#define NKV 8192
#define DDIM 512
static constexpr float QSCALE = 0.044194173824159216f; // 1/sqrt(512)

// ---------------- scratch (device globals; no allocation) ----------------
__device__ __align__(256) __half g_xh[NQ * DDIM];     // x fp16
__device__ __align__(256) __half g_domh[NKV * DDIM];  // dom fp16
__device__ __align__(256) __half g_wqh[DDIM * DDIM];  // Wq fp16
__device__ __align__(256) __half g_wkh[DDIM * DDIM];  // Wk fp16
__device__ __align__(256) __half g_wvh[DDIM * DDIM];  // Wv fp16

__device__ __align__(256) __half g_q[NQ * DDIM];      // q fp16 (scaled)
__device__ __align__(256) __half g_k[NKV * DDIM];     // k fp16
__device__ __align__(256) __half g_vt[DDIM * NKV];    // V^T fp16 [512, 8192]
__device__ __align__(256) __half g_p[(size_t)NQ * NKV];  // P = exp(scores), fp16
__device__ float g_lpart[(size_t)NQ * 128];   // [row][slot], row-major
__device__ float g_linv[NQ];

// ---------------- helpers ----------------
__device__ __forceinline__ uint32_t smem_u32(const void* p) {
    uint32_t a;
    asm("{ .reg .u64 t; cvta.to.shared.u64 t, %1; cvt.u32.u64 %0, t; }"
        : "=r"(a) : "l"(p));
    return a;
}

#define CP16(sa, gp) \
    asm volatile("cp.async.cg.shared.global [%0], [%1], 16;" \
                 :: "r"(sa), "l"(gp) : "memory")
#define CP_COMMIT asm volatile("cp.async.commit_group;" ::: "memory")
#define CP_WAITG(n) asm volatile("cp.async.wait_group %0;" :: "n"(n) : "memory")

#define LDSM_X4(r0, r1, r2, r3, addr) \
    asm volatile("ldmatrix.sync.aligned.m8n8.x4.shared.b16 {%0,%1,%2,%3}, [%4];" \
                 : "=r"(r0), "=r"(r1), "=r"(r2), "=r"(r3) : "r"(addr))

#define MMA_F16(d, a, b) \
    asm volatile("mma.sync.aligned.m16n8k16.row.col.f32.f16.f16.f32 " \
                 "{%0,%1,%2,%3}, {%4,%5,%6,%7}, {%8,%9}, {%0,%1,%2,%3};" \
                 : "+f"((d)[0]), "+f"((d)[1]), "+f"((d)[2]), "+f"((d)[3]) \
                 : "r"((a)[0]), "r"((a)[1]), "r"((a)[2]), "r"((a)[3]), \
                   "r"((b)[0]), "r"((b)[1]))

__device__ __forceinline__ uint2 pack4h(float a, float b, float c, float d) {
    uint2 r;
    __half2 lo = __floats2half2_rn(a, b), hi = __floats2half2_rn(c, d);
    r.x = *(uint32_t*)&lo; r.y = *(uint32_t*)&hi;
    return r;
}

// ---------------------------------------------------------------------------
// presplit: fp32 -> fp16. 1M threads, 4 floats each stream.
// ---------------------------------------------------------------------------
__global__ __launch_bounds__(256) void presplit_kernel(
    const float* __restrict__ x, const float* __restrict__ dom,
    const float* __restrict__ Wq, const float* __restrict__ Wk,
    const float* __restrict__ Wv)
{
    const int i = blockIdx.x * 256 + threadIdx.x;   // 0 .. 1048575

    {   // x -> fp16
        float4 v = ((const float4*)x)[i];
        ((uint2*)g_xh)[i] = pack4h(v.x, v.y, v.z, v.w);
    }
    {   // dom -> fp16
        float4 v = ((const float4*)dom)[i];
        ((uint2*)g_domh)[i] = pack4h(v.x, v.y, v.z, v.w);
    }
    if (i < (DDIM * DDIM) / 4) {
        {
            float4 v = ((const float4*)Wq)[i];
            ((uint2*)g_wqh)[i] = pack4h(v.x, v.y, v.z, v.w);
        }
        {
            float4 v = ((const float4*)Wk)[i];
            ((uint2*)g_wkh)[i] = pack4h(v.x, v.y, v.z, v.w);
        }
        {
            float4 v = ((const float4*)Wv)[i];
            ((uint2*)g_wvh)[i] = pack4h(v.x, v.y, v.z, v.w);
        }
    }
}

// ---------------------------------------------------------------------------
// proj_gemm: 128x128 tile, warp 32x64, single fp16 product, 2-stage, occ 2.
//   z=0: q  = (xh @ Wqh^T + bq) * QSCALE     [8192,512]
//   z=1: k  =  domh @ Wkh^T + bk             [8192,512]
//   z=2: vt =  Wvh @ domh^T + bv (row bias)  [512,8192]  (V^T directly)
// ---------------------------------------------------------------------------
#define ARRP_B   18432           // 128 rows * 144 B
#define STAGEP_B (2 * ARRP_B)    // A | B
#define SMEM_PJ  (2 * STAGEP_B)  // 73728

__global__ __launch_bounds__(256, 2) void proj_gemm_kernel(
    const float* __restrict__ bq, const float* __restrict__ bk,
    const float* __restrict__ bv)
{
    constexpr int NC = DDIM / 64;   // 8
    extern __shared__ char smc[];
    const uint32_t smb = smem_u32(smc);

    const int mode = blockIdx.z;
    const int bx = (mode == 2) ? blockIdx.x : blockIdx.y;   // n tile
    const int by = (mode == 2) ? blockIdx.y : blockIdx.x;   // m tile

    const __half* __restrict__ A  = (mode == 0) ? g_xh  : (mode == 1 ? g_domh : g_wvh);
    const __half* __restrict__ B  = (mode == 0) ? g_wqh : (mode == 1 ? g_wkh : g_domh);
    const float* __restrict__ bias = (mode == 0) ? bq : (mode == 1 ? bk : bv);
    __half* __restrict__ outp = (mode == 0) ? g_q : (mode == 1 ? g_k : g_vt);
    const int outLD = (mode == 2) ? NKV : DDIM;
    const float scale = (mode == 0) ? QSCALE : 1.0f;

    const int tid = threadIdx.x;
    const int lane = tid & 31, w = tid >> 5;
    const int wm = w & 3, wn = w >> 2;
    const int rowBase = by * 128;
    const int nBase = bx * 128;

    float acc[2][8][4];
#pragma unroll
    for (int i = 0; i < 2; ++i)
#pragma unroll
        for (int j = 0; j < 8; ++j)
#pragma unroll
            for (int e = 0; e < 4; ++e) acc[i][j][e] = 0.0f;

    auto load_stage = [&](int buf, int kc) {
        const int kBase = kc * 64;
        const uint32_t sb = smb + buf * STAGEP_B;
#pragma unroll
        for (int it = 0; it < 4; ++it) {
            int idx = tid + it * 256;
            int r = idx >> 3, cc = idx & 7;
            uint32_t so = (uint32_t)(r * 144 + cc * 16);
            CP16(sb + so,          A + (size_t)(rowBase + r) * DDIM + kBase + cc * 8);
            CP16(sb + ARRP_B + so, B + (size_t)(nBase + r) * DDIM + kBase + cc * 8);
        }
        CP_COMMIT;
    };

    const uint32_t aOff = (uint32_t)((wm * 32 + (lane & 15)) * 144 + ((lane >> 4) * 8) * 2);
    const int g = lane >> 3;
    const uint32_t bOff = (uint32_t)((wn * 64 + ((g >> 1) << 3) + (lane & 7)) * 144
                                     + ((g & 1) << 3) * 2);

    load_stage(0, 0);

#pragma unroll 1
    for (int c = 0; c < NC; ++c) {
        CP_WAITG(0);
        __syncthreads();
        if (c + 1 < NC) load_stage((c + 1) & 1, c + 1);

        const uint32_t sb = smb + (c & 1) * STAGEP_B;
        const uint32_t aA = sb + aOff;
        const uint32_t bB = sb + ARRP_B + bOff;
#pragma unroll
        for (int kk = 0; kk < 4; ++kk) {
            uint32_t av[2][4], bh[4][4];
#pragma unroll
            for (int i = 0; i < 2; ++i)
                LDSM_X4(av[i][0], av[i][1], av[i][2], av[i][3], aA + i * 2304 + kk * 32);
#pragma unroll
            for (int j = 0; j < 4; ++j)
                LDSM_X4(bh[j][0], bh[j][1], bh[j][2], bh[j][3], bB + j * 2304 + kk * 32);
#pragma unroll
            for (int i = 0; i < 2; ++i)
#pragma unroll
                for (int jj = 0; jj < 8; ++jj)
                    MMA_F16(acc[i][jj], av[i], &bh[jj >> 1][(jj & 1) * 2]);
        }
    }

    // ---- epilogue: bias (+scale) -> fp16 store ----
    if (mode == 2) {
#pragma unroll
        for (int i = 0; i < 2; ++i) {
            const int row0 = rowBase + wm * 32 + i * 16 + (lane >> 2);
            const float b0 = bias[row0], b1 = bias[row0 + 8];
#pragma unroll
            for (int jj = 0; jj < 8; ++jj) {
                const int col = nBase + wn * 64 + jj * 8 + (lane & 3) * 2;
                *(__half2*)&outp[(size_t)row0 * outLD + col] =
                    __floats2half2_rn(acc[i][jj][0] + b0, acc[i][jj][1] + b0);
                *(__half2*)&outp[(size_t)(row0 + 8) * outLD + col] =
                    __floats2half2_rn(acc[i][jj][2] + b1, acc[i][jj][3] + b1);
            }
        }
    } else {
#pragma unroll
        for (int i = 0; i < 2; ++i) {
            const int row0 = rowBase + wm * 32 + i * 16 + (lane >> 2);
#pragma unroll
            for (int jj = 0; jj < 8; ++jj) {
                const int col = nBase + wn * 64 + jj * 8 + (lane & 3) * 2;
                const float bc0 = bias[col], bc1 = bias[col + 1];
                *(__half2*)&outp[(size_t)row0 * outLD + col] =
                    __floats2half2_rn((acc[i][jj][0] + bc0) * scale,
                                      (acc[i][jj][1] + bc1) * scale);
                *(__half2*)&outp[(size_t)(row0 + 8) * outLD + col] =
                    __floats2half2_rn((acc[i][jj][2] + bc0) * scale,
                                      (acc[i][jj][3] + bc1) * scale);
            }
        }
    }
}

// ---------------------------------------------------------------------------
// Big-GEMM geometry: 128x128 tile, 8 warps (4m x 2n), warp 32x64, BK=64,
// 3-stage cp.async, 2 CTAs/SM, single fp16 product.
// ---------------------------------------------------------------------------
#define ARR_B    18432           // 128 rows * 144 B
#define STAGE_B  (2 * ARR_B)     // A | B
#define SMEM_GB  (3 * STAGE_B)   // 110592

// ---- GEMM1: P = exp(q k^T), K=512 ----
__global__ __launch_bounds__(256, 2) void gemm1_kernel()
{
    constexpr int NC = DDIM / 64;   // 8
    extern __shared__ char smc[];
    const uint32_t smb = smem_u32(smc);

    const int tid = threadIdx.x;
    const int lane = tid & 31, w = tid >> 5;
    const int wm = w & 3, wn = w >> 2;
    const int rowBase = blockIdx.y * 128;
    const int nBase = blockIdx.x * 128;

    float acc[2][8][4];
#pragma unroll
    for (int i = 0; i < 2; ++i)
#pragma unroll
        for (int j = 0; j < 8; ++j)
#pragma unroll
            for (int e = 0; e < 4; ++e) acc[i][j][e] = 0.0f;

    auto load_stage = [&](int buf, int kc) {
        const int kBase = kc * 64;
        const uint32_t sb = smb + buf * STAGE_B;
#pragma unroll
        for (int it = 0; it < 4; ++it) {
            int idx = tid + it * 256;
            int r = idx >> 3, cc = idx & 7;
            uint32_t so = (uint32_t)(r * 144 + cc * 16);
            CP16(sb + so,         g_q + (size_t)(rowBase + r) * DDIM + kBase + cc * 8);
            CP16(sb + ARR_B + so, g_k + (size_t)(nBase + r) * DDIM + kBase + cc * 8);
        }
        CP_COMMIT;
    };

    const uint32_t aOff = (uint32_t)((wm * 32 + (lane & 15)) * 144 + ((lane >> 4) * 8) * 2);
    const int g = lane >> 3;
    const uint32_t bOff = (uint32_t)((wn * 64 + ((g >> 1) << 3) + (lane & 7)) * 144
                                     + ((g & 1) << 3) * 2);

    load_stage(0, 0);
    load_stage(1, 1);

#pragma unroll 1
    for (int c = 0; c < NC; ++c) {
        if (c == NC - 1) { CP_WAITG(0); } else { CP_WAITG(1); }
        __syncthreads();
        if (c + 2 < NC) load_stage((c + 2) % 3, c + 2);

        const uint32_t sb = smb + (c % 3) * STAGE_B;
        const uint32_t aA = sb + aOff;
        const uint32_t bB = sb + ARR_B + bOff;
#pragma unroll
        for (int kk = 0; kk < 4; ++kk) {
            uint32_t aq[2][4], kb[4][4];
#pragma unroll
            for (int i = 0; i < 2; ++i)
                LDSM_X4(aq[i][0], aq[i][1], aq[i][2], aq[i][3], aA + i * 2304 + kk * 32);
#pragma unroll
            for (int j = 0; j < 4; ++j)
                LDSM_X4(kb[j][0], kb[j][1], kb[j][2], kb[j][3], bB + j * 2304 + kk * 32);
#pragma unroll
            for (int i = 0; i < 2; ++i)
#pragma unroll
                for (int jj = 0; jj < 8; ++jj)
                    MMA_F16(acc[i][jj], aq[i], &kb[jj >> 1][(jj & 1) * 2]);
        }
    }

    // ---- epilogue: P = exp(acc) -> fp16, plus deterministic row-sum partials
    float ls[2][2] = {{0.0f, 0.0f}, {0.0f, 0.0f}};
#pragma unroll
    for (int i = 0; i < 2; ++i) {
        const int row0 = rowBase + wm * 32 + i * 16 + (lane >> 2);
#pragma unroll
        for (int jj = 0; jj < 8; ++jj) {
            const int col = nBase + wn * 64 + jj * 8 + (lane & 3) * 2;
            float p0 = __expf(acc[i][jj][0]);
            float p1 = __expf(acc[i][jj][1]);
            float p2 = __expf(acc[i][jj][2]);
            float p3 = __expf(acc[i][jj][3]);
            ls[i][0] += p0 + p1;
            ls[i][1] += p2 + p3;
            *(__half2*)&g_p[(size_t)row0 * NKV + col] = __floats2half2_rn(p0, p1);
            *(__half2*)&g_p[(size_t)(row0 + 8) * NKV + col] = __floats2half2_rn(p2, p3);
        }
    }
    const int slot = blockIdx.x * 2 + wn;   // 0..127
#pragma unroll
    for (int i = 0; i < 2; ++i)
#pragma unroll
        for (int pr = 0; pr < 2; ++pr) {
            float s = ls[i][pr];
            s += __shfl_xor_sync(0xffffffffu, s, 1);
            s += __shfl_xor_sync(0xffffffffu, s, 2);
            if ((lane & 3) == 0) {
                int row = rowBase + wm * 32 + i * 16 + (lane >> 2) + pr * 8;
                g_lpart[(size_t)row * 128 + slot] = s;   // row-major
            }
        }
}

// ---- GEMM2: O = (P V) * linv, K=8192 ----
__global__ __launch_bounds__(256, 2) void gemm2_kernel(float* __restrict__ outp)
{
    constexpr int NC = NKV / 64;    // 128
    extern __shared__ char smc[];
    const uint32_t smb = smem_u32(smc);

    const int tid = threadIdx.x;
    const int lane = tid & 31, w = tid >> 5;
    const int wm = w & 3, wn = w >> 2;
    const int rowBase = blockIdx.y * 128;
    const int nBase = blockIdx.x * 128;

    float acc[2][8][4];
#pragma unroll
    for (int i = 0; i < 2; ++i)
#pragma unroll
        for (int j = 0; j < 8; ++j)
#pragma unroll
            for (int e = 0; e < 4; ++e) acc[i][j][e] = 0.0f;

    auto load_stage = [&](int buf, int kc) {
        const int kBase = kc * 64;
        const uint32_t sb = smb + buf * STAGE_B;
#pragma unroll
        for (int it = 0; it < 4; ++it) {
            int idx = tid + it * 256;
            int r = idx >> 3, cc = idx & 7;
            uint32_t so = (uint32_t)(r * 144 + cc * 16);
            CP16(sb + so,         g_p + (size_t)(rowBase + r) * NKV + kBase + cc * 8);
            CP16(sb + ARR_B + so, g_vt + (size_t)(nBase + r) * NKV + kBase + cc * 8);
        }
        CP_COMMIT;
    };

    const uint32_t aOff = (uint32_t)((wm * 32 + (lane & 15)) * 144 + ((lane >> 4) * 8) * 2);
    const int g = lane >> 3;
    const uint32_t bOff = (uint32_t)((wn * 64 + ((g >> 1) << 3) + (lane & 7)) * 144
                                     + ((g & 1) << 3) * 2);

    load_stage(0, 0);
    load_stage(1, 1);

#pragma unroll 1
    for (int c = 0; c < NC; ++c) {
        if (c == NC - 1) { CP_WAITG(0); } else { CP_WAITG(1); }
        __syncthreads();
        if (c + 2 < NC) load_stage((c + 2) % 3, c + 2);

        const uint32_t sb = smb + (c % 3) * STAGE_B;
        const uint32_t aP = sb + aOff;
        const uint32_t bV = sb + ARR_B + bOff;
#pragma unroll
        for (int kk = 0; kk < 4; ++kk) {
            uint32_t ap[2][4], vb[4][4];
#pragma unroll
            for (int i = 0; i < 2; ++i)
                LDSM_X4(ap[i][0], ap[i][1], ap[i][2], ap[i][3], aP + i * 2304 + kk * 32);
#pragma unroll
            for (int j = 0; j < 4; ++j)
                LDSM_X4(vb[j][0], vb[j][1], vb[j][2], vb[j][3], bV + j * 2304 + kk * 32);
#pragma unroll
            for (int i = 0; i < 2; ++i)
#pragma unroll
                for (int jj = 0; jj < 8; ++jj)
                    MMA_F16(acc[i][jj], ap[i], &vb[jj >> 1][(jj & 1) * 2]);
        }
    }

    // ---- epilogue: out = acc * linv[row]
#pragma unroll
    for (int i = 0; i < 2; ++i) {
        const int row0 = rowBase + wm * 32 + i * 16 + (lane >> 2);
        const float inv0 = g_linv[row0];
        const float inv1 = g_linv[row0 + 8];
#pragma unroll
        for (int jj = 0; jj < 8; ++jj) {
            const int col = nBase + wn * 64 + jj * 8 + (lane & 3) * 2;
            float2 r0, r1;
            r0.x = acc[i][jj][0] * inv0; r0.y = acc[i][jj][1] * inv0;
            r1.x = acc[i][jj][2] * inv1; r1.y = acc[i][jj][3] * inv1;
            *(float2*)&outp[(size_t)row0 * DDIM + col] = r0;
            *(float2*)&outp[(size_t)(row0 + 8) * DDIM + col] = r1;
        }
    }
}

// ---------------------------------------------------------------------------
// lred: one warp per row; row-major g_lpart -> coalesced float4 reads.
// ---------------------------------------------------------------------------
__global__ __launch_bounds__(256) void lred_kernel()
{
    const int row = blockIdx.x * 8 + (threadIdx.x >> 5);
    const int lane = threadIdx.x & 31;
    float4 v = ((const float4*)(g_lpart + (size_t)row * 128))[lane];
    float s = v.x + v.y + v.z + v.w;
#pragma unroll
    for (int off = 16; off > 0; off >>= 1)
        s += __shfl_xor_sync(0xffffffffu, s, off);
    if (lane == 0) g_linv[row] = 1.0f / s;
}

// ---------------------------------------------------------------------------
extern "C" void kernel_launch(void* const* d_in, const int* in_sizes, int n_in,
                              void* d_out, int out_size)
{
    const float* x   = (const float*)d_in[0];
    const float* dom = (const float*)d_in[1];
    const float* Wq  = (const float*)d_in[2];
    const float* bq  = (const float*)d_in[3];
    const float* Wk  = (const float*)d_in[4];
    const float* bk  = (const float*)d_in[5];
    const float* Wv  = (const float*)d_in[6];
    const float* bv  = (const float*)d_in[7];
    float* out = (float*)d_out;

    cudaFuncSetAttribute(proj_gemm_kernel,
                         cudaFuncAttributeMaxDynamicSharedMemorySize, SMEM_PJ);
    cudaFuncSetAttribute(gemm1_kernel,
                         cudaFuncAttributeMaxDynamicSharedMemorySize, SMEM_GB);
    cudaFuncSetAttribute(gemm2_kernel,
                         cudaFuncAttributeMaxDynamicSharedMemorySize, SMEM_GB);

    presplit_kernel<<<(NQ * DDIM / 4) / 256, 256>>>(x, dom, Wq, Wk, Wv);

    // q, k, vt projections on tensor cores (z: 0=q, 1=k, 2=vt)
    proj_gemm_kernel<<<dim3(64, 4, 3), 256, SMEM_PJ>>>(bq, bk, bv);

    // P = exp(q k^T)
    gemm1_kernel<<<dim3(NKV / 128, NQ / 128), 256, SMEM_GB>>>();

    lred_kernel<<<NQ / 8, 256>>>();

    // O = (P V) * linv
    gemm2_kernel<<<dim3(DDIM / 128, NQ / 128), 256, SMEM_GB>>>(out);
}